// round 2
// baseline (speedup 1.0000x reference)
#include <cuda_runtime.h>
#include <cstdint>

#define BATCH   16
#define NANCH   102000
#define NCLS    35
#define STRIDE  40          // 4 box + 1 obj + 35 cls
#define PRE     1024
#define MAXD    300
#define CONF_T  0.25f
#define IOU_T   0.45f
#define BINS    4096
#define EQCAP   1024

// ---------------- device scratch (no allocations allowed) ----------------
__device__ float    g_scores[BATCH * NANCH];
__device__ int      g_selidx[BATCH * PRE];
__device__ float    g_selscore[BATCH * PRE];
__device__ float    g_boxes[BATCH * PRE * 4];
__device__ float    g_cls[BATCH * PRE];
__device__ unsigned g_mask[BATCH * PRE * 32];

// ---------------- kernel 1: per-anchor confidence score ----------------
__global__ void score_kernel(const float* __restrict__ pred) {
    int i = blockIdx.x * blockDim.x + threadIdx.x;
    if (i >= BATCH * NANCH) return;
    const float4* p = (const float4*)(pred + (size_t)i * STRIDE);
    float vals[36];  // elements 4..39 (obj + 35 cls)
#pragma unroll
    for (int q = 0; q < 9; q++) {
        float4 v = p[1 + q];
        vals[q * 4 + 0] = v.x; vals[q * 4 + 1] = v.y;
        vals[q * 4 + 2] = v.z; vals[q * 4 + 3] = v.w;
    }
    float obj = vals[0];
    float conf = 0.0f;                       // products are >= 0
#pragma unroll
    for (int c = 0; c < NCLS; c++) {
        float pcs = __fmul_rn(vals[1 + c], obj);   // matches jnp cls*obj then max
        conf = fmaxf(conf, pcs);
    }
    float s = (obj > CONF_T && conf > CONF_T) ? conf : 0.0f;
    g_scores[i] = s;
}

// ---------------- kernel 2: exact top-1024 per batch (stable, jax tie order) ----
// key = (score_bits << 32) | (0xFFFFFFFF - index): desc sort => score desc, idx asc
__global__ void select_kernel() {
    int b = blockIdx.x, t = threadIdx.x;
    __shared__ unsigned hist[BINS];
    __shared__ unsigned psum[1024];
    __shared__ unsigned long long keys[PRE];
    __shared__ unsigned long long eqk[EQCAP];
    __shared__ int sB1;
    __shared__ unsigned sG;
    __shared__ unsigned cnt_gt, cnt_eq;

    const float* s = g_scores + (size_t)b * NANCH;
    for (int j = t; j < BINS; j += 1024) hist[j] = 0u;
    if (t == 0) { cnt_gt = 0u; cnt_eq = 0u; }
    __syncthreads();

    // histogram of fixed-point bins; skip zeros (huge duplicate mass)
    for (int j = t; j < NANCH; j += 1024) {
        float v = s[j];
        if (v > 0.0f) {
            int bin = (int)(v * 4096.0f); bin = bin > 4095 ? 4095 : bin;
            atomicAdd(&hist[bin], 1u);
        }
    }
    __syncthreads();

    unsigned h0 = hist[t * 4], h1 = hist[t * 4 + 1], h2 = hist[t * 4 + 2], h3 = hist[t * 4 + 3];
    psum[t] = h0 + h1 + h2 + h3;
    __syncthreads();
    // reversed inclusive Hillis-Steele: psum[t] = count(bins >= 4t)
    for (int off = 1; off < 1024; off <<= 1) {
        unsigned v = (t + off < 1024) ? psum[t + off] : 0u;
        __syncthreads();
        psum[t] += v;
        __syncthreads();
    }
    if (t == 0) { sB1 = 0; sG = (psum[0] < PRE) ? psum[0] : 0u; }  // fallback
    __syncthreads();
    {
        unsigned S4 = (t + 1 < 1024) ? psum[t + 1] : 0u;   // count(bins >= 4t+4)
        unsigned S3 = S4 + h3, S2 = S3 + h2, S1 = S2 + h1, S0 = S1 + h0;
        if (S3 >= PRE && S4 < PRE) { sB1 = 4 * t + 3; sG = S4; }
        if (S2 >= PRE && S3 < PRE) { sB1 = 4 * t + 2; sG = S3; }
        if (S1 >= PRE && S2 < PRE) { sB1 = 4 * t + 1; sG = S2; }
        if (S0 >= PRE && S1 < PRE) { sB1 = 4 * t + 0; sG = S1; }
    }
    eqk[t] = 0ull;
    __syncthreads();
    int B1 = sB1; unsigned G = sG;

    // gather: strictly-above bin -> keys; boundary bin -> eq buffer
    for (int j = t; j < NANCH; j += 1024) {
        float v = s[j];
        if (v > 0.0f) {
            int bin = (int)(v * 4096.0f); bin = bin > 4095 ? 4095 : bin;
            unsigned long long key =
                ((unsigned long long)__float_as_uint(v) << 32) |
                (unsigned long long)(0xFFFFFFFFu - (unsigned)j);
            if (bin > B1) {
                unsigned pos = atomicAdd(&cnt_gt, 1u);
                if (pos < PRE) keys[pos] = key;
            } else if (bin == B1) {
                unsigned pos = atomicAdd(&cnt_eq, 1u);
                if (pos < EQCAP) eqk[pos] = key;
            }
        }
    }
    __syncthreads();

    // bitonic sort eq buffer descending (small set; padded with 0)
    for (unsigned k = 2; k <= EQCAP; k <<= 1)
        for (unsigned j = k >> 1; j > 0; j >>= 1) {
            __syncthreads();
            unsigned i = t, l = i ^ j;
            if (l > i) {
                unsigned long long a = eqk[i], c = eqk[l];
                bool up = ((i & k) == 0);
                if (up ? (a < c) : (a > c)) { eqk[i] = c; eqk[l] = a; }
            }
        }
    __syncthreads();
    unsigned need = PRE - G;
    if (t < need) keys[G + t] = eqk[t];
    __syncthreads();

    // bitonic sort final 1024 keys descending
    for (unsigned k = 2; k <= PRE; k <<= 1)
        for (unsigned j = k >> 1; j > 0; j >>= 1) {
            __syncthreads();
            unsigned i = t, l = i ^ j;
            if (l > i) {
                unsigned long long a = keys[i], c = keys[l];
                bool up = ((i & k) == 0);
                if (up ? (a < c) : (a > c)) { keys[i] = c; keys[l] = a; }
            }
        }
    __syncthreads();
    unsigned long long kk = keys[t];
    g_selscore[b * PRE + t] = __uint_as_float((unsigned)(kk >> 32));
    g_selidx[b * PRE + t]   = (int)(0xFFFFFFFFu - (unsigned)(kk & 0xFFFFFFFFu));
}

// ---------------- kernel 3a: gather boxes + argmax class for selected ----------
__global__ void gather_kernel(const float* __restrict__ pred) {
    int i = blockIdx.x * blockDim.x + threadIdx.x;
    if (i >= BATCH * PRE) return;
    int b = i / PRE;
    int idx = g_selidx[i];
    if ((unsigned)idx >= NANCH) idx = 0;   // padded entry safety (score==0 anyway)
    const float* p = pred + ((size_t)b * NANCH + idx) * STRIDE;
    float x = p[0], y = p[1], w = p[2], h = p[3];
    float hw = __fmul_rn(w, 0.5f), hh = __fmul_rn(h, 0.5f);
    float4 bx;
    bx.x = __fsub_rn(x, hw); bx.y = __fsub_rn(y, hh);
    bx.z = __fadd_rn(x, hw); bx.w = __fadd_rn(y, hh);
    ((float4*)g_boxes)[i] = bx;
    float obj = p[4];
    int best = 0; float bv = __fmul_rn(p[5], obj);
#pragma unroll
    for (int c = 1; c < NCLS; c++) {
        float v = __fmul_rn(p[5 + c], obj);
        if (v > bv) { bv = v; best = c; }   // first-max, matches jnp.argmax
    }
    g_cls[i] = (float)best;
}

// ---------------- kernel 3b: 1024x1024 IoU>thresh bitmask (j>r only) ----------
__global__ void iou_kernel() {
    int b = blockIdx.y;
    int warp = threadIdx.x >> 5, lane = threadIdx.x & 31;
    int r = blockIdx.x * 8 + warp;
    __shared__ float4 sb[PRE];
    for (int j = threadIdx.x; j < PRE; j += 256)
        sb[j] = ((const float4*)g_boxes)[b * PRE + j];
    __syncthreads();
    float4 br = sb[r];
    float aw = fmaxf(__fsub_rn(br.z, br.x), 0.0f);
    float ah = fmaxf(__fsub_rn(br.w, br.y), 0.0f);
    float ar = __fmul_rn(aw, ah);
    unsigned myword = 0u;
#pragma unroll 4
    for (int w = 0; w < 32; w++) {
        int j = w * 32 + lane;
        bool pbit = false;
        if (j > r) {
            float4 bj = sb[j];
            float jw = fmaxf(__fsub_rn(bj.z, bj.x), 0.0f);
            float jh = fmaxf(__fsub_rn(bj.w, bj.y), 0.0f);
            float aj = __fmul_rn(jw, jh);
            float lx = fmaxf(br.x, bj.x), ly = fmaxf(br.y, bj.y);
            float rx = fminf(br.z, bj.z), ry = fminf(br.w, bj.w);
            float iw = fmaxf(__fsub_rn(rx, lx), 0.0f);
            float ih = fmaxf(__fsub_rn(ry, ly), 0.0f);
            float inter = __fmul_rn(iw, ih);
            float denom = __fadd_rn(__fsub_rn(__fadd_rn(ar, aj), inter), 1e-7f);
            pbit = (inter / denom) > IOU_T;
        }
        unsigned bits = __ballot_sync(0xffffffffu, pbit);
        if (lane == w) myword = bits;
    }
    g_mask[((size_t)b * PRE + r) * 32 + lane] = myword;
}

// ---------------- kernel 4: sequential NMS scan + top-300 output ----------------
__global__ void nms_kernel(float* __restrict__ out) {
    extern __shared__ unsigned sh[];
    unsigned* smask  = sh;                              // PRE*32 words
    float*    sscore = (float*)(sh + PRE * 32);         // PRE floats
    unsigned* skeep  = (unsigned*)(sscore + PRE);       // 32 words
    int b = blockIdx.x, t = threadIdx.x;

    const uint4* gm4 = (const uint4*)(g_mask + (size_t)b * PRE * 32);
    uint4* sm4 = (uint4*)smask;
    for (int j = t; j < PRE * 8; j += 1024) sm4[j] = gm4[j];
    for (int j = t; j < PRE; j += 1024) sscore[j] = g_selscore[b * PRE + j];
    __syncthreads();

    if (t < 32) {
        int l = t;
        unsigned sup = 0u, keepw = 0u;
        unsigned nxt = smask[l];            // row 0 prefetch
        for (int i = 0; i < PRE; i++) {
            unsigned row = nxt;
            if (i + 1 < PRE) nxt = smask[(i + 1) * 32 + l];  // hide LDS latency
            int w = i >> 5, bit = i & 31;
            int k = 0;
            if (l == w) {
                k = (sscore[i] > 0.0f) && !((sup >> bit) & 1u);
                if (k) keepw |= (1u << bit);
            }
            k = __shfl_sync(0xffffffffu, k, w);
            if (k) sup |= row;
        }
        skeep[l] = keepw;
    }
    __syncthreads();

    // output mapping: kept entries in order, then lowest-index non-kept (score 0)
    int w = t >> 5, bit = t & 31;
    int rank = 0, total = 0;
#pragma unroll
    for (int q = 0; q < 32; q++) {
        int pc = __popc(skeep[q]);
        if (q < w) rank += pc;
        total += pc;
    }
    rank += __popc(skeep[w] & ((1u << bit) - 1u));
    bool kp = (skeep[w] >> bit) & 1u;
    int orow = -1; float osc = 0.0f;
    if (kp) {
        if (rank < MAXD) { orow = rank; osc = sscore[t]; }
    } else {
        int nr = t - rank;
        if (total + nr < MAXD) orow = total + nr;   // fill rows, score 0
    }
    if (orow >= 0) {
        float4 bx = ((const float4*)g_boxes)[b * PRE + t];
        float cc = g_cls[b * PRE + t];
        float* o = out + ((size_t)b * MAXD + orow) * 6;
        o[0] = bx.x; o[1] = bx.y; o[2] = bx.z; o[3] = bx.w;
        o[4] = osc;  o[5] = cc;
    }
}

// ---------------- launch ----------------
extern "C" void kernel_launch(void* const* d_in, const int* in_sizes, int n_in,
                              void* d_out, int out_size) {
    const float* pred = (const float*)d_in[0];
    float* out = (float*)d_out;

    const int nms_smem = (PRE * 32 + PRE + 32) * 4;   // 135296 bytes
    cudaFuncSetAttribute(nms_kernel, cudaFuncAttributeMaxDynamicSharedMemorySize, nms_smem);

    score_kernel<<<(BATCH * NANCH + 255) / 256, 256>>>(pred);
    select_kernel<<<BATCH, 1024>>>();
    gather_kernel<<<(BATCH * PRE + 255) / 256, 256>>>(pred);
    iou_kernel<<<dim3(128, BATCH), 256>>>();
    nms_kernel<<<BATCH, 1024, nms_smem>>>(out);
}

// round 3
// speedup vs baseline: 1.5003x; 1.5003x over previous
#include <cuda_runtime.h>
#include <cstdint>

#define BATCH   16
#define NANCH   102000
#define NCLS    35
#define STRIDE  40          // 4 box + 1 obj + 35 cls
#define PRE     1024
#define MAXD    300
#define CONF_T  0.25f
#define IOU_T   0.45f
#define BINS    4096

// ---------------- device scratch ----------------
__device__ float    g_scores[BATCH * NANCH];
__device__ unsigned g_hist[BATCH * BINS];
__device__ unsigned g_cnt[BATCH * 2];            // [b*2]=gt count, [b*2+1]=eq count
__device__ int      g_B1[BATCH];
__device__ unsigned g_G[BATCH];
__device__ unsigned long long g_keys[BATCH * PRE];
__device__ unsigned long long g_eqkeys[BATCH * PRE];
__device__ int      g_selidx[BATCH * PRE];
__device__ float    g_selscore[BATCH * PRE];
__device__ float    g_boxes[BATCH * PRE * 4];
__device__ float    g_cls[BATCH * PRE];
__device__ unsigned g_mask[BATCH * PRE * 32];

// ---------------- kernel 1: score + global histogram ----------------
__global__ void score_kernel(const float* __restrict__ pred) {
    int i = blockIdx.x * blockDim.x + threadIdx.x;
    int b = blockIdx.y;
    if (i >= NANCH) return;
    const float4* p = (const float4*)(pred + ((size_t)b * NANCH + i) * STRIDE);
    float vals[36];
#pragma unroll
    for (int q = 0; q < 9; q++) {
        float4 v = p[1 + q];
        vals[q * 4 + 0] = v.x; vals[q * 4 + 1] = v.y;
        vals[q * 4 + 2] = v.z; vals[q * 4 + 3] = v.w;
    }
    float obj = vals[0];
    float conf = 0.0f;
#pragma unroll
    for (int c = 0; c < NCLS; c++) {
        float pcs = __fmul_rn(vals[1 + c], obj);
        conf = fmaxf(conf, pcs);
    }
    float s = (obj > CONF_T && conf > CONF_T) ? conf : 0.0f;
    g_scores[(size_t)b * NANCH + i] = s;
    if (s > 0.0f) {
        int bin = (int)(s * 4096.0f); bin = bin > 4095 ? 4095 : bin;
        atomicAdd(&g_hist[b * BINS + bin], 1u);
    }
}

// ---------------- kernel 2: threshold bin per batch ----------------
__global__ void thresh_kernel() {
    int b = blockIdx.x, t = threadIdx.x;
    __shared__ unsigned psum[1024];
    __shared__ int sB1;
    __shared__ unsigned sG;
    uint4 h = ((const uint4*)(g_hist + b * BINS))[t];
    psum[t] = h.x + h.y + h.z + h.w;
    __syncthreads();
    for (int off = 1; off < 1024; off <<= 1) {
        unsigned v = (t + off < 1024) ? psum[t + off] : 0u;
        __syncthreads();
        psum[t] += v;
        __syncthreads();
    }
    if (t == 0) { sB1 = 0; sG = (psum[0] < PRE) ? psum[0] : 0u; }
    __syncthreads();
    {
        unsigned S4 = (t + 1 < 1024) ? psum[t + 1] : 0u;
        unsigned S3 = S4 + h.w, S2 = S3 + h.z, S1 = S2 + h.y, S0 = S1 + h.x;
        if (S3 >= PRE && S4 < PRE) { sB1 = 4 * t + 3; sG = S4; }
        if (S2 >= PRE && S3 < PRE) { sB1 = 4 * t + 2; sG = S3; }
        if (S1 >= PRE && S2 < PRE) { sB1 = 4 * t + 1; sG = S2; }
        if (S0 >= PRE && S1 < PRE) { sB1 = 4 * t + 0; sG = S1; }
    }
    __syncthreads();
    if (t == 0) { g_B1[b] = sB1; g_G[b] = sG; }
}

// ---------------- kernel 3: parallel gather of candidate keys ----------------
__global__ void gatherk_kernel() {
    int j = blockIdx.x * blockDim.x + threadIdx.x;
    int b = blockIdx.y;
    if (j >= NANCH) return;
    float v = g_scores[(size_t)b * NANCH + j];
    if (v <= 0.0f) return;
    int bin = (int)(v * 4096.0f); bin = bin > 4095 ? 4095 : bin;
    int B1 = g_B1[b];
    if (bin < B1) return;
    unsigned long long key =
        ((unsigned long long)__float_as_uint(v) << 32) |
        (unsigned long long)(0xFFFFFFFFu - (unsigned)j);
    if (bin > B1) {
        unsigned pos = atomicAdd(&g_cnt[b * 2], 1u);
        if (pos < PRE) g_keys[b * PRE + pos] = key;
    } else {
        unsigned pos = atomicAdd(&g_cnt[b * 2 + 1], 1u);
        if (pos < PRE) g_eqkeys[b * PRE + pos] = key;
    }
}

// ---------------- kernel 4: per-batch sort (16 blocks) ----------------
__device__ __forceinline__ void bitonic1024(unsigned long long* a, int t) {
    for (unsigned k = 2; k <= 1024; k <<= 1)
        for (unsigned j = k >> 1; j > 0; j >>= 1) {
            __syncthreads();
            unsigned i = t, l = i ^ j;
            if (l > i) {
                unsigned long long x = a[i], y = a[l];
                bool up = ((i & k) == 0);
                if (up ? (x < y) : (x > y)) { a[i] = y; a[l] = x; }
            }
        }
    __syncthreads();
}

__global__ void sort_kernel() {
    int b = blockIdx.x, t = threadIdx.x;
    __shared__ unsigned long long keys[PRE];
    __shared__ unsigned long long eq[PRE];
    unsigned G = g_G[b]; if (G > PRE) G = PRE;
    unsigned eqc = g_cnt[b * 2 + 1]; if (eqc > PRE) eqc = PRE;
    keys[t] = (t < (int)G) ? g_keys[b * PRE + t] : 0ull;
    eq[t]   = (t < (int)eqc) ? g_eqkeys[b * PRE + t] : 0ull;
    bitonic1024(eq, t);
    unsigned need = PRE - G;
    if (t < (int)need) keys[G + t] = eq[t];
    bitonic1024(keys, t);
    unsigned long long kk = keys[t];
    g_selscore[b * PRE + t] = __uint_as_float((unsigned)(kk >> 32));
    g_selidx[b * PRE + t]   = (int)(0xFFFFFFFFu - (unsigned)(kk & 0xFFFFFFFFu));
}

// ---------------- kernel 5: gather boxes + argmax class ----------------
__global__ void gather_kernel(const float* __restrict__ pred) {
    int i = blockIdx.x * blockDim.x + threadIdx.x;
    if (i >= BATCH * PRE) return;
    int b = i / PRE;
    int idx = g_selidx[i];
    if ((unsigned)idx >= NANCH) idx = 0;
    const float* p = pred + ((size_t)b * NANCH + idx) * STRIDE;
    float x = p[0], y = p[1], w = p[2], h = p[3];
    float hw = __fmul_rn(w, 0.5f), hh = __fmul_rn(h, 0.5f);
    float4 bx;
    bx.x = __fsub_rn(x, hw); bx.y = __fsub_rn(y, hh);
    bx.z = __fadd_rn(x, hw); bx.w = __fadd_rn(y, hh);
    ((float4*)g_boxes)[i] = bx;
    float obj = p[4];
    int best = 0; float bv = __fmul_rn(p[5], obj);
#pragma unroll
    for (int c = 1; c < NCLS; c++) {
        float v = __fmul_rn(p[5 + c], obj);
        if (v > bv) { bv = v; best = c; }
    }
    g_cls[i] = (float)best;
}

// ---------------- kernel 6: IoU bitmask, lane=word, no ballots ----------------
__global__ void iou_kernel() {
    int b = blockIdx.y;
    int warp = threadIdx.x >> 5, lane = threadIdx.x & 31;
    int r = blockIdx.x * 8 + warp;
    __shared__ float4 sb[PRE];
    __shared__ float  sa[PRE];
    for (int j = threadIdx.x; j < PRE; j += 256) {
        float4 v = ((const float4*)g_boxes)[b * PRE + j];
        sb[j] = v;
        float w0 = fmaxf(__fsub_rn(v.z, v.x), 0.0f);
        float h0 = fmaxf(__fsub_rn(v.w, v.y), 0.0f);
        sa[j] = __fmul_rn(w0, h0);
    }
    __syncthreads();
    float4 br = sb[r];
    float ar = sa[r];
    unsigned word = 0u;
    if (32 * lane + 31 > r) {
#pragma unroll
        for (int k = 0; k < 32; k++) {
            int j = 32 * lane + k;
            if (j > r) {
                float4 bj = sb[j];
                float aj = sa[j];
                float lx = fmaxf(br.x, bj.x), ly = fmaxf(br.y, bj.y);
                float rx = fminf(br.z, bj.z), ry = fminf(br.w, bj.w);
                float iw = fmaxf(__fsub_rn(rx, lx), 0.0f);
                float ih = fmaxf(__fsub_rn(ry, ly), 0.0f);
                float inter = __fmul_rn(iw, ih);
                float denom = __fadd_rn(__fsub_rn(__fadd_rn(ar, aj), inter), 1e-7f);
                if ((inter / denom) > IOU_T) word |= (1u << k);
            }
        }
    }
    g_mask[((size_t)b * PRE + r) * 32 + lane] = word;
}

// ---------------- kernel 7: word-parallel NMS scan + top-300 output ----------------
__global__ void __launch_bounds__(128) nms_kernel(float* __restrict__ out) {
    __shared__ float    sscore[PRE];
    __shared__ unsigned svalid[32];
    __shared__ unsigned skeep[32];
    __shared__ unsigned kpre[33];
    int b = blockIdx.x, t = threadIdx.x;

    // load scores + validity words
    for (int it = 0; it < 8; it++) {
        int e = it * 128 + t;
        float sc = g_selscore[b * PRE + e];
        sscore[e] = sc;
        unsigned bl = __ballot_sync(0xffffffffu, sc > 0.0f);
        if ((t & 31) == 0) svalid[it * 4 + (t >> 5)] = bl;
    }
    __syncthreads();

    if (t < 32) {
        const unsigned* M = g_mask + (size_t)b * PRE * 32 + t;  // column t
        unsigned sup = 0u, mykeep = 0u;
        unsigned m[32], mn[32];
#pragma unroll
        for (int k = 0; k < 32; k++) m[k] = M[(size_t)k * 32];
        for (int w = 0; w < 32; w++) {
            int wn = (w + 1 < 32) ? (w + 1) : 31;
#pragma unroll
            for (int k = 0; k < 32; k++) mn[k] = M[((size_t)(wn * 32 + k)) * 32];
            unsigned kw = 0u;
            if (t == w) {
                unsigned s = sup, vw = svalid[w];
#pragma unroll
                for (int k = 0; k < 32; k++) {
                    unsigned bit = 1u << k;
                    if ((vw & bit) && !(s & bit)) { kw |= bit; s |= m[k]; }
                }
                sup = s;
            }
            kw = __shfl_sync(0xffffffffu, kw, w);
            if (t == w) {
                mykeep = kw;
            } else {
#pragma unroll
                for (int k = 0; k < 32; k++)
                    if (kw & (1u << k)) sup |= m[k];
            }
#pragma unroll
            for (int k = 0; k < 32; k++) m[k] = mn[k];
        }
        skeep[t] = mykeep;
    }
    __syncthreads();

    if (t < 32) {
        unsigned acc = 0;
        for (int q = 0; q < 32; q++) {
            if (q == t) kpre[t] = acc;
            acc += __popc(skeep[q]);
        }
        if (t == 0) kpre[32] = acc;   // wrong slot guard; fixed below
    }
    __syncthreads();
    if (t == 0) {
        unsigned tot = 0;
        for (int q = 0; q < 32; q++) tot += __popc(skeep[q]);
        kpre[32] = tot;
    }
    __syncthreads();
    unsigned total = kpre[32];

    for (int e = t; e < PRE; e += 128) {
        int w = e >> 5, bit = e & 31;
        int rank = kpre[w] + __popc(skeep[w] & ((1u << bit) - 1u));
        bool kp = (skeep[w] >> bit) & 1u;
        int orow = -1; float osc = 0.0f;
        if (kp) {
            if (rank < MAXD) { orow = rank; osc = sscore[e]; }
        } else {
            int nr = e - rank;
            if ((int)total + nr < MAXD) orow = (int)total + nr;
        }
        if (orow >= 0) {
            float4 bx = ((const float4*)g_boxes)[b * PRE + e];
            float cc = g_cls[b * PRE + e];
            float* o = out + ((size_t)b * MAXD + orow) * 6;
            o[0] = bx.x; o[1] = bx.y; o[2] = bx.z; o[3] = bx.w;
            o[4] = osc;  o[5] = cc;
        }
    }
}

// ---------------- launch ----------------
extern "C" void kernel_launch(void* const* d_in, const int* in_sizes, int n_in,
                              void* d_out, int out_size) {
    const float* pred = (const float*)d_in[0];
    float* out = (float*)d_out;

    void *hist_ptr = nullptr, *cnt_ptr = nullptr;
    cudaGetSymbolAddress(&hist_ptr, g_hist);
    cudaGetSymbolAddress(&cnt_ptr, g_cnt);
    cudaMemsetAsync(hist_ptr, 0, BATCH * BINS * sizeof(unsigned));
    cudaMemsetAsync(cnt_ptr, 0, BATCH * 2 * sizeof(unsigned));

    dim3 gs((NANCH + 255) / 256, BATCH);
    score_kernel<<<gs, 256>>>(pred);
    thresh_kernel<<<BATCH, 1024>>>();
    gatherk_kernel<<<gs, 256>>>();
    sort_kernel<<<BATCH, 1024>>>();
    gather_kernel<<<(BATCH * PRE + 255) / 256, 256>>>(pred);
    iou_kernel<<<dim3(PRE / 8, BATCH), 256>>>();
    nms_kernel<<<BATCH, 128>>>(out);
}

// round 8
// speedup vs baseline: 2.1655x; 1.4434x over previous
#include <cuda_runtime.h>
#include <cstdint>

#define BATCH   16
#define NANCH   102000
#define NCLS    35
#define STRIDE  40          // 4 box + 1 obj + 35 cls
#define PRE     1024
#define MAXD    300
#define CONF_T  0.25f
#define IOU_T   0.45f
#define BINS    4096

// ---------------- device scratch ----------------
__device__ __align__(16) float    g_scores[BATCH * NANCH];
__device__ __align__(16) unsigned g_hist[BATCH * BINS];      // zero-init; self-cleaned
__device__ __align__(16) float    g_selscore[BATCH * PRE];
__device__ __align__(16) float    g_boxes[BATCH * PRE * 4];
__device__ __align__(16) float    g_cls[BATCH * PRE];
__device__ __align__(16) unsigned g_mask[BATCH * PRE * 32];

// ---------------- kernel 1: score + histogram (smem-staged, coalesced) ----------
__global__ void __launch_bounds__(256) score_kernel(const float* __restrict__ pred) {
    __shared__ float st[256 * 41];              // 41-float stride: conflict-free reads
    int b = blockIdx.y;
    int a0 = blockIdx.x * 256;
    int nrem = NANCH - a0; if (nrem > 256) nrem = 256;
    const float4* gp = (const float4*)(pred + ((size_t)b * NANCH + a0) * STRIDE);
    int nv4 = nrem * 10;                        // 10 float4 per anchor
    for (int g = threadIdx.x; g < nv4; g += 256) {
        float4 v = gp[g];
        int anchor = g / 10;
        int ew = (g - anchor * 10) * 4;
        float* d = st + anchor * 41 + ew;
        d[0] = v.x; d[1] = v.y; d[2] = v.z; d[3] = v.w;
    }
    __syncthreads();
    int t = threadIdx.x;
    if (t < nrem) {
        const float* s = st + t * 41;
        float obj = s[4];
        float conf = 0.0f;
#pragma unroll
        for (int c = 0; c < NCLS; c++)
            conf = fmaxf(conf, __fmul_rn(s[5 + c], obj));
        float sc = (obj > CONF_T && conf > CONF_T) ? conf : 0.0f;
        g_scores[(size_t)b * NANCH + a0 + t] = sc;
        if (sc > 0.0f) {
            int bin = (int)(sc * 4096.0f); bin = bin > 4095 ? 4095 : bin;
            atomicAdd(&g_hist[b * BINS + bin], 1u);
        }
    }
}

// ---------------- register-resident bitonic sort (descending, 1024 u64) ----------
__device__ __forceinline__ unsigned long long bmerge(unsigned long long v,
                                                     unsigned long long p,
                                                     bool keepmax) {
    return keepmax ? (v > p ? v : p) : (v < p ? v : p);
}

__device__ unsigned long long bitonic1024_desc(unsigned long long* a, int t) {
    unsigned long long v = a[t];
#pragma unroll
    for (unsigned k = 2; k <= 32; k <<= 1) {
#pragma unroll
        for (unsigned j = k >> 1; j > 0; j >>= 1) {
            unsigned long long p = __shfl_xor_sync(0xffffffffu, v, j);
            bool keepmax = ((t & k) == 0) == ((t & j) == 0);
            v = bmerge(v, p, keepmax);
        }
    }
    for (unsigned k = 64; k <= 1024; k <<= 1) {
        for (unsigned j = k >> 1; j >= 32; j >>= 1) {
            __syncthreads();
            a[t] = v;
            __syncthreads();
            unsigned long long p = a[t ^ j];
            bool keepmax = ((t & k) == 0) == ((t & j) == 0);
            v = bmerge(v, p, keepmax);
        }
#pragma unroll
        for (unsigned j = 16; j > 0; j >>= 1) {
            unsigned long long p = __shfl_xor_sync(0xffffffffu, v, j);
            bool keepmax = ((t & k) == 0) == ((t & j) == 0);
            v = bmerge(v, p, keepmax);
        }
    }
    __syncthreads();
    a[t] = v;
    __syncthreads();
    return v;
}

// -------- kernel 2 (fused): threshold + gather + sort + box/cls gather ----------
__global__ void __launch_bounds__(1024) select_kernel(const float* __restrict__ pred) {
    int b = blockIdx.x, t = threadIdx.x;
    int lane = t & 31, w = t >> 5;
    __shared__ unsigned long long keys[PRE];
    __shared__ unsigned long long eq[PRE];
    __shared__ unsigned warpsum[32];
    __shared__ int sB1;
    __shared__ unsigned sG;
    __shared__ unsigned cgt, ceq;

    // --- threshold via histogram suffix-scan ---
    uint4 h = ((const uint4*)(g_hist + b * BINS))[t];
    ((uint4*)(g_hist + b * BINS))[t] = make_uint4(0u, 0u, 0u, 0u);  // self-clean
    unsigned s = h.x + h.y + h.z + h.w;
    unsigned sacc = s;
#pragma unroll
    for (int o = 1; o < 32; o <<= 1) {
        unsigned v = __shfl_down_sync(0xffffffffu, sacc, o);
        if (lane + o < 32) sacc += v;
    }
    if (lane == 0) warpsum[w] = sacc;
    keys[t] = 0ull; eq[t] = 0ull;
    if (t == 0) { cgt = 0u; ceq = 0u; }
    __syncthreads();
    if (t < 32) {
        unsigned ws = warpsum[t];
        unsigned wacc = ws;
#pragma unroll
        for (int o = 1; o < 32; o <<= 1) {
            unsigned v = __shfl_down_sync(0xffffffffu, wacc, o);
            if (t + o < 32) wacc += v;
        }
        warpsum[t] = wacc - ws;     // exclusive suffix over warps
    }
    __syncthreads();
    unsigned S_incl = sacc + warpsum[w];     // count(bins >= 4t)
    if (t == 0) { sB1 = 0; sG = (S_incl < PRE) ? S_incl : 0u; }
    __syncthreads();
    {
        unsigned S4 = S_incl - s;            // count(bins >= 4t+4)
        unsigned S3 = S4 + h.w, S2 = S3 + h.z, S1 = S2 + h.y, S0 = S1 + h.x;
        if (S3 >= PRE && S4 < PRE) { sB1 = 4 * t + 3; sG = S4; }
        if (S2 >= PRE && S3 < PRE) { sB1 = 4 * t + 2; sG = S3; }
        if (S1 >= PRE && S2 < PRE) { sB1 = 4 * t + 1; sG = S2; }
        if (S0 >= PRE && S1 < PRE) { sB1 = 4 * t + 0; sG = S1; }
    }
    __syncthreads();
    int B1 = sB1;
    unsigned G = sG; if (G > PRE) G = PRE;

    // --- gather candidate keys from this batch's scores (float4, coalesced) ---
    const float4* sp = (const float4*)(g_scores + (size_t)b * NANCH);
    for (int j4 = t; j4 < NANCH / 4; j4 += 1024) {
        float4 v4 = sp[j4];
        float vv[4] = {v4.x, v4.y, v4.z, v4.w};
#pragma unroll
        for (int c = 0; c < 4; c++) {
            float v = vv[c];
            if (v > 0.0f) {
                int bin = (int)(v * 4096.0f); bin = bin > 4095 ? 4095 : bin;
                unsigned j = 4 * j4 + c;
                unsigned long long key =
                    ((unsigned long long)__float_as_uint(v) << 32) |
                    (unsigned long long)(0xFFFFFFFFu - j);
                if (bin > B1) {
                    unsigned pos = atomicAdd(&cgt, 1u);
                    if (pos < PRE) keys[pos] = key;
                } else if (bin == B1) {
                    unsigned pos = atomicAdd(&ceq, 1u);
                    if (pos < PRE) eq[pos] = key;
                }
            }
        }
    }
    __syncthreads();

    // --- sort boundary bin, splice, sort final 1024 ---
    bitonic1024_desc(eq, t);
    unsigned need = PRE - G;
    if (t < (int)need) keys[G + t] = eq[t];
    __syncthreads();
    unsigned long long kk = bitonic1024_desc(keys, t);

    // --- emit score + gather box/class for own element ---
    float sc = __uint_as_float((unsigned)(kk >> 32));
    unsigned idxu = 0xFFFFFFFFu - (unsigned)(kk & 0xFFFFFFFFu);
    int ai = (idxu < NANCH) ? (int)idxu : 0;
    g_selscore[b * PRE + t] = sc;
    const float4* p = (const float4*)(pred + ((size_t)b * NANCH + ai) * STRIDE);
    float4 xywh = p[0];
    float hw = __fmul_rn(xywh.z, 0.5f), hh = __fmul_rn(xywh.w, 0.5f);
    float4 bx;
    bx.x = __fsub_rn(xywh.x, hw); bx.y = __fsub_rn(xywh.y, hh);
    bx.z = __fadd_rn(xywh.x, hw); bx.w = __fadd_rn(xywh.y, hh);
    ((float4*)g_boxes)[b * PRE + t] = bx;
    // argmax over obj*cls, first-max semantics (class c at word 5+c)
    float4 r0 = p[1];                 // words 4..7: obj, cls0, cls1, cls2
    float obj = r0.x;
    int best = 0; float bv = __fmul_rn(r0.y, obj);
    { float v1 = __fmul_rn(r0.z, obj); if (v1 > bv) { bv = v1; best = 1; }
      float v2 = __fmul_rn(r0.w, obj); if (v2 > bv) { bv = v2; best = 2; } }
#pragma unroll
    for (int q = 2; q <= 9; q++) {
        float4 rq = p[q];             // words 4q..4q+3 -> classes 4q-5 .. 4q-2
        int cb = 4 * q - 5;
        float v0 = __fmul_rn(rq.x, obj); if (v0 > bv) { bv = v0; best = cb + 0; }
        float v1 = __fmul_rn(rq.y, obj); if (v1 > bv) { bv = v1; best = cb + 1; }
        float v2 = __fmul_rn(rq.z, obj); if (v2 > bv) { bv = v2; best = cb + 2; }
        float v3 = __fmul_rn(rq.w, obj); if (v3 > bv) { bv = v3; best = cb + 3; }
    }
    g_cls[b * PRE + t] = (float)best;
}

// ---------------- kernel 3: IoU bitmask (skewed SoA smem, gated div) ----------
__global__ void __launch_bounds__(256) iou_kernel() {
    int b = blockIdx.y;
    int warp = threadIdx.x >> 5, lane = threadIdx.x & 31;
    int r = blockIdx.x * 8 + warp;
    __shared__ float sx1[1056], sy1[1056], sx2[1056], sy2[1056], sar[1056];
    for (int j = threadIdx.x; j < PRE; j += 256) {
        float4 v = ((const float4*)g_boxes)[b * PRE + j];
        int jj = j + (j >> 5);                 // skew: lane-stride-32 -> conflict-free
        sx1[jj] = v.x; sy1[jj] = v.y; sx2[jj] = v.z; sy2[jj] = v.w;
        float w0 = fmaxf(__fsub_rn(v.z, v.x), 0.0f);
        float h0 = fmaxf(__fsub_rn(v.w, v.y), 0.0f);
        sar[jj] = __fmul_rn(w0, h0);
    }
    __syncthreads();
    int rr = r + (r >> 5);
    float bx1 = sx1[rr], by1 = sy1[rr], bx2 = sx2[rr], by2 = sy2[rr], ar = sar[rr];
    unsigned word = 0u;
    int jbase = lane * 32;
    if (jbase + 31 > r) {
        int jjb = lane * 33;
#pragma unroll
        for (int k = 0; k < 32; k++) {
            int j = jbase + k;
            if (j > r) {
                float lx = fmaxf(bx1, sx1[jjb + k]), ly = fmaxf(by1, sy1[jjb + k]);
                float rx = fminf(bx2, sx2[jjb + k]), ry = fminf(by2, sy2[jjb + k]);
                float iw = fmaxf(__fsub_rn(rx, lx), 0.0f);
                float ih = fmaxf(__fsub_rn(ry, ly), 0.0f);
                float inter = __fmul_rn(iw, ih);
                if (inter > 0.0f) {            // iou==0 can't exceed 0.45
                    float aj = sar[jjb + k];
                    float denom = __fadd_rn(__fsub_rn(__fadd_rn(ar, aj), inter), 1e-7f);
                    if ((inter / denom) > IOU_T) word |= (1u << k);
                }
            }
        }
    }
    g_mask[((size_t)b * PRE + r) * 32 + lane] = word;
}

// ---------------- kernel 4: word-parallel NMS scan + top-300 output ------------
__global__ void __launch_bounds__(128) nms_kernel(float* __restrict__ out) {
    __shared__ float    sscore[PRE];
    __shared__ unsigned svalid[32];
    __shared__ unsigned skeep[32];
    __shared__ unsigned kpre[33];
    int b = blockIdx.x, t = threadIdx.x;

    for (int it = 0; it < 8; it++) {
        int e = it * 128 + t;
        float sc = g_selscore[b * PRE + e];
        sscore[e] = sc;
        unsigned bl = __ballot_sync(0xffffffffu, sc > 0.0f);
        if ((t & 31) == 0) svalid[it * 4 + (t >> 5)] = bl;
    }
    __syncthreads();

    if (t < 32) {
        const unsigned* M = g_mask + (size_t)b * PRE * 32 + t;   // column t
        unsigned sup = 0u, mykeep = 0u;
        unsigned m[32], mn[32];
#pragma unroll
        for (int k = 0; k < 32; k++) m[k] = M[(size_t)k * 32];
        for (int w = 0; w < 32; w++) {
            int wn = (w + 1 < 32) ? (w + 1) : 31;
#pragma unroll
            for (int k = 0; k < 32; k++) mn[k] = M[((size_t)(wn * 32 + k)) * 32];
            unsigned kw = 0u;
            if (t == w) {
                unsigned ss = sup, vw = svalid[w];
#pragma unroll
                for (int k = 0; k < 32; k++) {
                    unsigned bit = 1u << k;
                    if ((vw & bit) && !(ss & bit)) { kw |= bit; ss |= m[k]; }
                }
                sup = ss;
            }
            kw = __shfl_sync(0xffffffffu, kw, w);
            if (t == w) {
                mykeep = kw;
            } else {
#pragma unroll
                for (int k = 0; k < 32; k++)
                    if (kw & (1u << k)) sup |= m[k];
            }
#pragma unroll
            for (int k = 0; k < 32; k++) m[k] = mn[k];
        }
        skeep[t] = mykeep;
    }
    __syncthreads();

    if (t < 32) {
        unsigned acc = 0;
        for (int q = 0; q < 32; q++) {
            if (q == t) kpre[t] = acc;
            acc += __popc(skeep[q]);
        }
        if (t == 31) kpre[32] = acc;
    }
    __syncthreads();
    unsigned total = kpre[32];

    for (int e = t; e < PRE; e += 128) {
        int w = e >> 5, bit = e & 31;
        int rank = kpre[w] + __popc(skeep[w] & ((1u << bit) - 1u));
        bool kp = (skeep[w] >> bit) & 1u;
        int orow = -1; float osc = 0.0f;
        if (kp) {
            if (rank < MAXD) { orow = rank; osc = sscore[e]; }
        } else {
            int nr = e - rank;
            if ((int)total + nr < MAXD) orow = (int)total + nr;
        }
        if (orow >= 0) {
            float4 bx = ((const float4*)g_boxes)[b * PRE + e];
            float cc = g_cls[b * PRE + e];
            float* o = out + ((size_t)b * MAXD + orow) * 6;
            o[0] = bx.x; o[1] = bx.y; o[2] = bx.z; o[3] = bx.w;
            o[4] = osc;  o[5] = cc;
        }
    }
}

// ---------------- launch ----------------
extern "C" void kernel_launch(void* const* d_in, const int* in_sizes, int n_in,
                              void* d_out, int out_size) {
    const float* pred = (const float*)d_in[0];
    float* out = (float*)d_out;

    dim3 gs((NANCH + 255) / 256, BATCH);
    score_kernel<<<gs, 256>>>(pred);
    select_kernel<<<BATCH, 1024>>>(pred);
    iou_kernel<<<dim3(PRE / 8, BATCH), 256>>>();
    nms_kernel<<<BATCH, 128>>>(out);
}

// round 11
// speedup vs baseline: 2.2379x; 1.0334x over previous
#include <cuda_runtime.h>
#include <cstdint>

#define BATCH   16
#define NANCH   102000
#define NCLS    35
#define STRIDE  40          // 4 box + 1 obj + 35 cls
#define PRE     1024
#define MAXD    300
#define CONF_T  0.25f
#define IOU_T   0.45f
#define BINS    4096

// ---------------- device scratch (all self-cleaning across graph replays) -------
__device__ __align__(16) float    g_scores[BATCH * NANCH];
__device__ __align__(16) unsigned g_hist[BATCH * BINS];   // zeroed by thresh_kernel
__device__ __align__(16) int      g_B1[BATCH];
__device__ __align__(16) unsigned g_G[BATCH];
__device__ __align__(16) unsigned g_cnt[BATCH * 2];       // zeroed by sortg_kernel
__device__ __align__(16) unsigned long long g_keys[BATCH * PRE];
__device__ __align__(16) unsigned long long g_eqkeys[BATCH * PRE];
__device__ __align__(16) float    g_selscore[BATCH * PRE];
__device__ __align__(16) float    g_boxes[BATCH * PRE * 4];
__device__ __align__(16) float    g_cls[BATCH * PRE];
__device__ __align__(16) unsigned g_mask[BATCH * PRE * 32];

// ---------------- kernel 1: score + histogram (smem-staged, coalesced) ----------
__global__ void __launch_bounds__(256) score_kernel(const float* __restrict__ pred) {
    __shared__ float st[256 * 41];              // 41-float stride: conflict-free reads
    int b = blockIdx.y;
    int a0 = blockIdx.x * 256;
    int nrem = NANCH - a0; if (nrem > 256) nrem = 256;
    const float4* gp = (const float4*)(pred + ((size_t)b * NANCH + a0) * STRIDE);
    int nv4 = nrem * 10;                        // 10 float4 per anchor
    for (int g = threadIdx.x; g < nv4; g += 256) {
        float4 v = gp[g];
        int anchor = g / 10;
        int ew = (g - anchor * 10) * 4;
        float* d = st + anchor * 41 + ew;
        d[0] = v.x; d[1] = v.y; d[2] = v.z; d[3] = v.w;
    }
    __syncthreads();
    int t = threadIdx.x;
    if (t < nrem) {
        const float* s = st + t * 41;
        float obj = s[4];
        float conf = 0.0f;
#pragma unroll
        for (int c = 0; c < NCLS; c++)
            conf = fmaxf(conf, __fmul_rn(s[5 + c], obj));
        float sc = (obj > CONF_T && conf > CONF_T) ? conf : 0.0f;
        g_scores[(size_t)b * NANCH + a0 + t] = sc;
        if (sc > 0.0f) {
            int bin = (int)(sc * 4096.0f); bin = bin > 4095 ? 4095 : bin;
            atomicAdd(&g_hist[b * BINS + bin], 1u);
        }
    }
}

// ---------------- kernel 2: threshold bin per batch (self-cleans hist) ----------
__global__ void __launch_bounds__(1024) thresh_kernel() {
    int b = blockIdx.x, t = threadIdx.x;
    int lane = t & 31, w = t >> 5;
    __shared__ unsigned warpsum[32];
    __shared__ int sB1;
    __shared__ unsigned sG;
    uint4 h = ((const uint4*)(g_hist + b * BINS))[t];
    ((uint4*)(g_hist + b * BINS))[t] = make_uint4(0u, 0u, 0u, 0u);  // self-clean
    unsigned s = h.x + h.y + h.z + h.w;
    unsigned sacc = s;
#pragma unroll
    for (int o = 1; o < 32; o <<= 1) {
        unsigned v = __shfl_down_sync(0xffffffffu, sacc, o);
        if (lane + o < 32) sacc += v;
    }
    if (lane == 0) warpsum[w] = sacc;
    __syncthreads();
    if (t < 32) {
        unsigned ws = warpsum[t];
        unsigned wacc = ws;
#pragma unroll
        for (int o = 1; o < 32; o <<= 1) {
            unsigned v = __shfl_down_sync(0xffffffffu, wacc, o);
            if (t + o < 32) wacc += v;
        }
        warpsum[t] = wacc - ws;     // exclusive suffix over warps
    }
    __syncthreads();
    unsigned S_incl = sacc + warpsum[w];     // count(bins >= 4t)
    if (t == 0) { sB1 = 0; sG = (S_incl < PRE) ? S_incl : 0u; }
    __syncthreads();
    {
        unsigned S4 = S_incl - s;            // count(bins >= 4t+4)
        unsigned S3 = S4 + h.w, S2 = S3 + h.z, S1 = S2 + h.y, S0 = S1 + h.x;
        if (S3 >= PRE && S4 < PRE) { sB1 = 4 * t + 3; sG = S4; }
        if (S2 >= PRE && S3 < PRE) { sB1 = 4 * t + 2; sG = S3; }
        if (S1 >= PRE && S2 < PRE) { sB1 = 4 * t + 1; sG = S2; }
        if (S0 >= PRE && S1 < PRE) { sB1 = 4 * t + 0; sG = S1; }
    }
    __syncthreads();
    if (t == 0) { g_B1[b] = sB1; g_G[b] = sG; }
}

// ---------------- kernel 3: grid-wide candidate gather (atomic append) ----------
__global__ void __launch_bounds__(256) gatherk_kernel() {
    int b = blockIdx.y;
    int j4 = blockIdx.x * 256 + threadIdx.x;
    if (j4 >= (NANCH + 3) / 4) return;
    int B1 = g_B1[b];
    const float4* sp = (const float4*)(g_scores + (size_t)b * NANCH);
    float4 v4 = sp[j4];                        // NANCH % 4 == 0
    float vv[4] = {v4.x, v4.y, v4.z, v4.w};
#pragma unroll
    for (int c = 0; c < 4; c++) {
        float v = vv[c];
        if (v > 0.0f) {
            int bin = (int)(v * 4096.0f); bin = bin > 4095 ? 4095 : bin;
            if (bin >= B1) {
                unsigned j = 4 * j4 + c;
                unsigned long long key =
                    ((unsigned long long)__float_as_uint(v) << 32) |
                    (unsigned long long)(0xFFFFFFFFu - j);
                if (bin > B1) {
                    unsigned pos = atomicAdd(&g_cnt[b * 2], 1u);
                    if (pos < PRE) g_keys[b * PRE + pos] = key;
                } else {
                    unsigned pos = atomicAdd(&g_cnt[b * 2 + 1], 1u);
                    if (pos < PRE) g_eqkeys[b * PRE + pos] = key;
                }
            }
        }
    }
}

// ---------------- register-resident bitonic sort (descending, 1024 u64) ----------
__device__ __forceinline__ unsigned long long bmerge(unsigned long long v,
                                                     unsigned long long p,
                                                     bool keepmax) {
    return keepmax ? (v > p ? v : p) : (v < p ? v : p);
}

__device__ unsigned long long bitonic1024_desc(unsigned long long* a, int t) {
    unsigned long long v = a[t];
#pragma unroll
    for (unsigned k = 2; k <= 32; k <<= 1) {
#pragma unroll
        for (unsigned j = k >> 1; j > 0; j >>= 1) {
            unsigned long long p = __shfl_xor_sync(0xffffffffu, v, j);
            bool keepmax = ((t & k) == 0) == ((t & j) == 0);
            v = bmerge(v, p, keepmax);
        }
    }
    for (unsigned k = 64; k <= 1024; k <<= 1) {
        for (unsigned j = k >> 1; j >= 32; j >>= 1) {
            __syncthreads();
            a[t] = v;
            __syncthreads();
            unsigned long long p = a[t ^ j];
            bool keepmax = ((t & k) == 0) == ((t & j) == 0);
            v = bmerge(v, p, keepmax);
        }
#pragma unroll
        for (unsigned j = 16; j > 0; j >>= 1) {
            unsigned long long p = __shfl_xor_sync(0xffffffffu, v, j);
            bool keepmax = ((t & k) == 0) == ((t & j) == 0);
            v = bmerge(v, p, keepmax);
        }
    }
    __syncthreads();
    a[t] = v;
    __syncthreads();
    return v;
}

// ---------------- kernel 4: sort + box/cls gather (self-cleans counters) --------
__global__ void __launch_bounds__(1024) sortg_kernel(const float* __restrict__ pred) {
    int b = blockIdx.x, t = threadIdx.x;
    __shared__ unsigned long long keys[PRE];
    __shared__ unsigned long long eq[PRE];
    unsigned G = g_G[b]; if (G > PRE) G = PRE;
    unsigned eqc = g_cnt[b * 2 + 1]; if (eqc > PRE) eqc = PRE;
    keys[t] = (t < (int)G) ? g_keys[b * PRE + t] : 0ull;
    eq[t]   = (t < (int)eqc) ? g_eqkeys[b * PRE + t] : 0ull;
    if (t == 0) { g_cnt[b * 2] = 0u; g_cnt[b * 2 + 1] = 0u; }   // self-clean
    __syncthreads();
    bitonic1024_desc(eq, t);
    unsigned need = PRE - G;
    if (t < (int)need) keys[G + t] = eq[t];
    __syncthreads();
    unsigned long long kk = bitonic1024_desc(keys, t);

    float sc = __uint_as_float((unsigned)(kk >> 32));
    unsigned idxu = 0xFFFFFFFFu - (unsigned)(kk & 0xFFFFFFFFu);
    int ai = (idxu < NANCH) ? (int)idxu : 0;
    g_selscore[b * PRE + t] = sc;
    const float4* p = (const float4*)(pred + ((size_t)b * NANCH + ai) * STRIDE);
    float4 xywh = p[0];
    float hw = __fmul_rn(xywh.z, 0.5f), hh = __fmul_rn(xywh.w, 0.5f);
    float4 bx;
    bx.x = __fsub_rn(xywh.x, hw); bx.y = __fsub_rn(xywh.y, hh);
    bx.z = __fadd_rn(xywh.x, hw); bx.w = __fadd_rn(xywh.y, hh);
    ((float4*)g_boxes)[b * PRE + t] = bx;
    // argmax over obj*cls, first-max semantics (class c at word 5+c)
    float4 r0 = p[1];                 // words 4..7: obj, cls0, cls1, cls2
    float obj = r0.x;
    int best = 0; float bv = __fmul_rn(r0.y, obj);
    { float v1 = __fmul_rn(r0.z, obj); if (v1 > bv) { bv = v1; best = 1; }
      float v2 = __fmul_rn(r0.w, obj); if (v2 > bv) { bv = v2; best = 2; } }
#pragma unroll
    for (int q = 2; q <= 9; q++) {
        float4 rq = p[q];             // words 4q..4q+3 -> classes 4q-5 .. 4q-2
        int cb = 4 * q - 5;
        float v0 = __fmul_rn(rq.x, obj); if (v0 > bv) { bv = v0; best = cb + 0; }
        float v1 = __fmul_rn(rq.y, obj); if (v1 > bv) { bv = v1; best = cb + 1; }
        float v2 = __fmul_rn(rq.z, obj); if (v2 > bv) { bv = v2; best = cb + 2; }
        float v3 = __fmul_rn(rq.w, obj); if (v3 > bv) { bv = v3; best = cb + 3; }
    }
    g_cls[b * PRE + t] = (float)best;
}

// ---------------- kernel 5: IoU bitmask (skewed SoA smem, gated div) ----------
__global__ void __launch_bounds__(256) iou_kernel() {
    int b = blockIdx.y;
    int warp = threadIdx.x >> 5, lane = threadIdx.x & 31;
    int r = blockIdx.x * 8 + warp;
    __shared__ float sx1[1056], sy1[1056], sx2[1056], sy2[1056], sar[1056];
    for (int j = threadIdx.x; j < PRE; j += 256) {
        float4 v = ((const float4*)g_boxes)[b * PRE + j];
        int jj = j + (j >> 5);                 // skew: lane-stride-32 -> conflict-free
        sx1[jj] = v.x; sy1[jj] = v.y; sx2[jj] = v.z; sy2[jj] = v.w;
        float w0 = fmaxf(__fsub_rn(v.z, v.x), 0.0f);
        float h0 = fmaxf(__fsub_rn(v.w, v.y), 0.0f);
        sar[jj] = __fmul_rn(w0, h0);
    }
    __syncthreads();
    int rr = r + (r >> 5);
    float bx1 = sx1[rr], by1 = sy1[rr], bx2 = sx2[rr], by2 = sy2[rr], ar = sar[rr];
    unsigned word = 0u;
    int jbase = lane * 32;
    if (jbase + 31 > r) {
        int jjb = lane * 33;
#pragma unroll
        for (int k = 0; k < 32; k++) {
            int j = jbase + k;
            if (j > r) {
                float lx = fmaxf(bx1, sx1[jjb + k]), ly = fmaxf(by1, sy1[jjb + k]);
                float rx = fminf(bx2, sx2[jjb + k]), ry = fminf(by2, sy2[jjb + k]);
                float iw = fmaxf(__fsub_rn(rx, lx), 0.0f);
                float ih = fmaxf(__fsub_rn(ry, ly), 0.0f);
                float inter = __fmul_rn(iw, ih);
                if (inter > 0.0f) {            // iou==0 can't exceed 0.45
                    float aj = sar[jjb + k];
                    float denom = __fadd_rn(__fsub_rn(__fadd_rn(ar, aj), inter), 1e-7f);
                    if ((inter / denom) > IOU_T) word |= (1u << k);
                }
            }
        }
    }
    g_mask[((size_t)b * PRE + r) * 32 + lane] = word;
}

// ---------------- kernel 6: NMS scan over smem-staged masks + top-300 out -------
__global__ void __launch_bounds__(256) nms_kernel(float* __restrict__ out) {
    extern __shared__ unsigned sh[];
    unsigned* smask  = sh;                          // PRE*32 words (128 KB)
    float*    sscore = (float*)(sh + PRE * 32);     // PRE floats
    __shared__ unsigned svalid[32];
    __shared__ unsigned skeep[32];
    __shared__ unsigned kpre[33];
    int b = blockIdx.x, t = threadIdx.x;

    // stage masks (coalesced uint4) + scores/validity
    const uint4* gm4 = (const uint4*)(g_mask + (size_t)b * PRE * 32);
    uint4* sm4 = (uint4*)smask;
    for (int j = t; j < PRE * 8; j += 256) sm4[j] = gm4[j];
    for (int it = 0; it < 4; it++) {
        int e = it * 256 + t;
        float sc = g_selscore[b * PRE + e];
        sscore[e] = sc;
        unsigned bl = __ballot_sync(0xffffffffu, sc > 0.0f);
        if ((t & 31) == 0) svalid[it * 8 + (t >> 5)] = bl;
    }
    __syncthreads();

    // warp 0: word-parallel scan (lane = distributed suppression word)
    if (t < 32) {
        unsigned sup = 0u, mykeep = 0u;
        for (int w = 0; w < 32; w++) {
            unsigned m[32];
#pragma unroll
            for (int k = 0; k < 32; k++) m[k] = smask[(w * 32 + k) * 32 + t];
            unsigned kw = 0u;
            if (t == w) {
                unsigned ss = sup, vw = svalid[w];
#pragma unroll
                for (int k = 0; k < 32; k++) {
                    unsigned bit = 1u << k;
                    if ((vw & bit) && !(ss & bit)) { kw |= bit; ss |= m[k]; }
                }
                sup = ss;
            }
            kw = __shfl_sync(0xffffffffu, kw, w);
            if (t == w) {
                mykeep = kw;
            } else {
#pragma unroll
                for (int k = 0; k < 32; k++)
                    if (kw & (1u << k)) sup |= m[k];
            }
        }
        skeep[t] = mykeep;
    }
    __syncthreads();

    if (t < 32) {
        unsigned acc = 0;
        for (int q = 0; q < 32; q++) {
            if (q == t) kpre[t] = acc;
            acc += __popc(skeep[q]);
        }
        if (t == 31) kpre[32] = acc;
    }
    __syncthreads();
    unsigned total = kpre[32];

    for (int e = t; e < PRE; e += 256) {
        int w = e >> 5, bit = e & 31;
        int rank = kpre[w] + __popc(skeep[w] & ((1u << bit) - 1u));
        bool kp = (skeep[w] >> bit) & 1u;
        int orow = -1; float osc = 0.0f;
        if (kp) {
            if (rank < MAXD) { orow = rank; osc = sscore[e]; }
        } else {
            int nr = e - rank;
            if ((int)total + nr < MAXD) orow = (int)total + nr;
        }
        if (orow >= 0) {
            float4 bx = ((const float4*)g_boxes)[b * PRE + e];
            float cc = g_cls[b * PRE + e];
            float* o = out + ((size_t)b * MAXD + orow) * 6;
            o[0] = bx.x; o[1] = bx.y; o[2] = bx.z; o[3] = bx.w;
            o[4] = osc;  o[5] = cc;
        }
    }
}

// ---------------- launch ----------------
extern "C" void kernel_launch(void* const* d_in, const int* in_sizes, int n_in,
                              void* d_out, int out_size) {
    const float* pred = (const float*)d_in[0];
    float* out = (float*)d_out;

    const int nms_smem = (PRE * 32 + PRE) * 4;      // 135168 bytes
    cudaFuncSetAttribute(nms_kernel, cudaFuncAttributeMaxDynamicSharedMemorySize, nms_smem);

    score_kernel<<<dim3((NANCH + 255) / 256, BATCH), 256>>>(pred);
    thresh_kernel<<<BATCH, 1024>>>();
    gatherk_kernel<<<dim3((NANCH / 4 + 255) / 256, BATCH), 256>>>();
    sortg_kernel<<<BATCH, 1024>>>(pred);
    iou_kernel<<<dim3(PRE / 8, BATCH), 256>>>();
    nms_kernel<<<BATCH, 256, nms_smem>>>(out);
}

// round 12
// speedup vs baseline: 2.2784x; 1.0181x over previous
#include <cuda_runtime.h>
#include <cstdint>

#define BATCH   16
#define NANCH   102000
#define NCLS    35
#define STRIDE  40          // 4 box + 1 obj + 35 cls
#define PRE     1024
#define MAXD    300
#define CONF_T  0.25f
#define IOU_T   0.45f
#define BINS    4096

// ---------------- device scratch (all self-cleaning across graph replays) -------
__device__ __align__(16) float    g_scores[BATCH * NANCH];
__device__ __align__(16) unsigned g_hist[BATCH * BINS];   // zeroed by thresh_kernel
__device__ __align__(16) int      g_B1[BATCH];
__device__ __align__(16) unsigned g_G[BATCH];
__device__ __align__(16) unsigned g_cnt[BATCH * 2];       // zeroed by sortg_kernel
__device__ __align__(16) unsigned long long g_keys[BATCH * PRE];
__device__ __align__(16) unsigned long long g_eqkeys[BATCH * PRE];
__device__ __align__(16) float    g_selscore[BATCH * PRE];
__device__ __align__(16) float    g_boxes[BATCH * PRE * 4];
__device__ __align__(16) float    g_cls[BATCH * PRE];
__device__ __align__(16) unsigned g_mask[BATCH * PRE * 32];

// ---------------- kernel 1: score + histogram (smem-staged, coalesced) ----------
__global__ void __launch_bounds__(256) score_kernel(const float* __restrict__ pred) {
    __shared__ float st[256 * 41];              // 41-float stride: conflict-free reads
    int b = blockIdx.y;
    int a0 = blockIdx.x * 256;
    int nrem = NANCH - a0; if (nrem > 256) nrem = 256;
    const float4* gp = (const float4*)(pred + ((size_t)b * NANCH + a0) * STRIDE);
    int nv4 = nrem * 10;                        // 10 float4 per anchor
    for (int g = threadIdx.x; g < nv4; g += 256) {
        float4 v = gp[g];
        int anchor = g / 10;
        int ew = (g - anchor * 10) * 4;
        float* d = st + anchor * 41 + ew;
        d[0] = v.x; d[1] = v.y; d[2] = v.z; d[3] = v.w;
    }
    __syncthreads();
    int t = threadIdx.x;
    if (t < nrem) {
        const float* s = st + t * 41;
        float obj = s[4];
        float conf = 0.0f;
#pragma unroll
        for (int c = 0; c < NCLS; c++)
            conf = fmaxf(conf, __fmul_rn(s[5 + c], obj));
        float sc = (obj > CONF_T && conf > CONF_T) ? conf : 0.0f;
        g_scores[(size_t)b * NANCH + a0 + t] = sc;
        if (sc > 0.0f) {
            int bin = (int)(sc * 4096.0f); bin = bin > 4095 ? 4095 : bin;
            atomicAdd(&g_hist[b * BINS + bin], 1u);
        }
    }
}

// ---------------- kernel 2: threshold bin per batch (self-cleans hist) ----------
__global__ void __launch_bounds__(1024) thresh_kernel() {
    int b = blockIdx.x, t = threadIdx.x;
    int lane = t & 31, w = t >> 5;
    __shared__ unsigned warpsum[32];
    __shared__ int sB1;
    __shared__ unsigned sG;
    uint4 h = ((const uint4*)(g_hist + b * BINS))[t];
    ((uint4*)(g_hist + b * BINS))[t] = make_uint4(0u, 0u, 0u, 0u);  // self-clean
    unsigned s = h.x + h.y + h.z + h.w;
    unsigned sacc = s;
#pragma unroll
    for (int o = 1; o < 32; o <<= 1) {
        unsigned v = __shfl_down_sync(0xffffffffu, sacc, o);
        if (lane + o < 32) sacc += v;
    }
    if (lane == 0) warpsum[w] = sacc;
    __syncthreads();
    if (t < 32) {
        unsigned ws = warpsum[t];
        unsigned wacc = ws;
#pragma unroll
        for (int o = 1; o < 32; o <<= 1) {
            unsigned v = __shfl_down_sync(0xffffffffu, wacc, o);
            if (t + o < 32) wacc += v;
        }
        warpsum[t] = wacc - ws;     // exclusive suffix over warps
    }
    __syncthreads();
    unsigned S_incl = sacc + warpsum[w];     // count(bins >= 4t)
    if (t == 0) { sB1 = 0; sG = (S_incl < PRE) ? S_incl : 0u; }
    __syncthreads();
    {
        unsigned S4 = S_incl - s;            // count(bins >= 4t+4)
        unsigned S3 = S4 + h.w, S2 = S3 + h.z, S1 = S2 + h.y, S0 = S1 + h.x;
        if (S3 >= PRE && S4 < PRE) { sB1 = 4 * t + 3; sG = S4; }
        if (S2 >= PRE && S3 < PRE) { sB1 = 4 * t + 2; sG = S3; }
        if (S1 >= PRE && S2 < PRE) { sB1 = 4 * t + 1; sG = S2; }
        if (S0 >= PRE && S1 < PRE) { sB1 = 4 * t + 0; sG = S1; }
    }
    __syncthreads();
    if (t == 0) { g_B1[b] = sB1; g_G[b] = sG; }
}

// ---------------- kernel 3: grid-wide candidate gather (atomic append) ----------
__global__ void __launch_bounds__(256) gatherk_kernel() {
    int b = blockIdx.y;
    int j4 = blockIdx.x * 256 + threadIdx.x;
    if (j4 >= (NANCH + 3) / 4) return;
    int B1 = g_B1[b];
    const float4* sp = (const float4*)(g_scores + (size_t)b * NANCH);
    float4 v4 = sp[j4];                        // NANCH % 4 == 0
    float vv[4] = {v4.x, v4.y, v4.z, v4.w};
#pragma unroll
    for (int c = 0; c < 4; c++) {
        float v = vv[c];
        if (v > 0.0f) {
            int bin = (int)(v * 4096.0f); bin = bin > 4095 ? 4095 : bin;
            if (bin >= B1) {
                unsigned j = 4 * j4 + c;
                unsigned long long key =
                    ((unsigned long long)__float_as_uint(v) << 32) |
                    (unsigned long long)(0xFFFFFFFFu - j);
                if (bin > B1) {
                    unsigned pos = atomicAdd(&g_cnt[b * 2], 1u);
                    if (pos < PRE) g_keys[b * PRE + pos] = key;
                } else {
                    unsigned pos = atomicAdd(&g_cnt[b * 2 + 1], 1u);
                    if (pos < PRE) g_eqkeys[b * PRE + pos] = key;
                }
            }
        }
    }
}

// ---------------- register-resident bitonic sort (descending, 1024 u64) ----------
__device__ __forceinline__ unsigned long long bmerge(unsigned long long v,
                                                     unsigned long long p,
                                                     bool keepmax) {
    return keepmax ? (v > p ? v : p) : (v < p ? v : p);
}

__device__ unsigned long long bitonic1024_desc(unsigned long long* a, int t) {
    unsigned long long v = a[t];
#pragma unroll
    for (unsigned k = 2; k <= 32; k <<= 1) {
#pragma unroll
        for (unsigned j = k >> 1; j > 0; j >>= 1) {
            unsigned long long p = __shfl_xor_sync(0xffffffffu, v, j);
            bool keepmax = ((t & k) == 0) == ((t & j) == 0);
            v = bmerge(v, p, keepmax);
        }
    }
    for (unsigned k = 64; k <= 1024; k <<= 1) {
        for (unsigned j = k >> 1; j >= 32; j >>= 1) {
            __syncthreads();
            a[t] = v;
            __syncthreads();
            unsigned long long p = a[t ^ j];
            bool keepmax = ((t & k) == 0) == ((t & j) == 0);
            v = bmerge(v, p, keepmax);
        }
#pragma unroll
        for (unsigned j = 16; j > 0; j >>= 1) {
            unsigned long long p = __shfl_xor_sync(0xffffffffu, v, j);
            bool keepmax = ((t & k) == 0) == ((t & j) == 0);
            v = bmerge(v, p, keepmax);
        }
    }
    __syncthreads();
    a[t] = v;
    __syncthreads();
    return v;
}

// ---- single-warp register bitonic-256 (descending), 8 elems/lane, no barriers ----
// element index i = e*32 + lane; j<32 -> shfl partner, j>=32 -> in-thread exchange
__device__ __forceinline__ void warp_bitonic256_desc(unsigned long long v[8], int lane) {
    for (unsigned k = 2; k <= 256; k <<= 1) {
        for (unsigned j = k >> 1; j > 0; j >>= 1) {
            if (j >= 32) {
                int es = (int)(j >> 5);
#pragma unroll
                for (int e = 0; e < 8; e++) {
                    int pe = e ^ es;
                    if (pe > e) {               // e has j-bit 0 -> (i&j)==0
                        unsigned i = (unsigned)(e * 32 + lane);
                        bool keepmax = ((i & k) == 0);
                        unsigned long long a = v[e], bb = v[pe];
                        unsigned long long hi = a > bb ? a : bb;
                        unsigned long long lo = a > bb ? bb : a;
                        v[e]  = keepmax ? hi : lo;
                        v[pe] = keepmax ? lo : hi;
                    }
                }
            } else {
#pragma unroll
                for (int e = 0; e < 8; e++) {
                    unsigned long long p = __shfl_xor_sync(0xffffffffu, v[e], j);
                    unsigned i = (unsigned)(e * 32 + lane);
                    bool keepmax = ((i & k) == 0) == ((i & j) == 0);
                    v[e] = bmerge(v[e], p, keepmax);
                }
            }
        }
    }
}

// ---------------- kernel 4: sort + box/cls gather (self-cleans counters) --------
__global__ void __launch_bounds__(1024) sortg_kernel(const float* __restrict__ pred) {
    int b = blockIdx.x, t = threadIdx.x;
    __shared__ unsigned long long keys[PRE];
    __shared__ unsigned long long eq[PRE];
    unsigned G = g_G[b]; if (G > PRE) G = PRE;
    unsigned eqc = g_cnt[b * 2 + 1]; if (eqc > PRE) eqc = PRE;
    keys[t] = (t < (int)G) ? g_keys[b * PRE + t] : 0ull;
    eq[t]   = (t < (int)eqc) ? g_eqkeys[b * PRE + t] : 0ull;
    if (t == 0) { g_cnt[b * 2] = 0u; g_cnt[b * 2 + 1] = 0u; }   // self-clean
    __syncthreads();

    // sort the boundary-bin keys descending.
    // common case (eqc <= 256): single-warp register sort, no block barriers.
    // note G + eqc >= PRE, so need = PRE-G <= eqc <= 256 is guaranteed to fit.
    if (eqc <= 256) {
        if (t < 32) {
            unsigned long long v[8];
#pragma unroll
            for (int e = 0; e < 8; e++) v[e] = eq[e * 32 + t];
            warp_bitonic256_desc(v, t);
#pragma unroll
            for (int e = 0; e < 8; e++) eq[e * 32 + t] = v[e];
        }
        __syncthreads();
    } else {
        bitonic1024_desc(eq, t);
    }

    unsigned need = PRE - G;
    if (t < (int)need) keys[G + t] = eq[t];
    __syncthreads();
    unsigned long long kk = bitonic1024_desc(keys, t);

    float sc = __uint_as_float((unsigned)(kk >> 32));
    unsigned idxu = 0xFFFFFFFFu - (unsigned)(kk & 0xFFFFFFFFu);
    int ai = (idxu < NANCH) ? (int)idxu : 0;
    g_selscore[b * PRE + t] = sc;
    const float4* p = (const float4*)(pred + ((size_t)b * NANCH + ai) * STRIDE);
    float4 xywh = p[0];
    float hw = __fmul_rn(xywh.z, 0.5f), hh = __fmul_rn(xywh.w, 0.5f);
    float4 bx;
    bx.x = __fsub_rn(xywh.x, hw); bx.y = __fsub_rn(xywh.y, hh);
    bx.z = __fadd_rn(xywh.x, hw); bx.w = __fadd_rn(xywh.y, hh);
    ((float4*)g_boxes)[b * PRE + t] = bx;
    // argmax over obj*cls, first-max semantics (class c at word 5+c)
    float4 r0 = p[1];                 // words 4..7: obj, cls0, cls1, cls2
    float obj = r0.x;
    int best = 0; float bv = __fmul_rn(r0.y, obj);
    { float v1 = __fmul_rn(r0.z, obj); if (v1 > bv) { bv = v1; best = 1; }
      float v2 = __fmul_rn(r0.w, obj); if (v2 > bv) { bv = v2; best = 2; } }
#pragma unroll
    for (int q = 2; q <= 9; q++) {
        float4 rq = p[q];             // words 4q..4q+3 -> classes 4q-5 .. 4q-2
        int cb = 4 * q - 5;
        float v0 = __fmul_rn(rq.x, obj); if (v0 > bv) { bv = v0; best = cb + 0; }
        float v1 = __fmul_rn(rq.y, obj); if (v1 > bv) { bv = v1; best = cb + 1; }
        float v2 = __fmul_rn(rq.z, obj); if (v2 > bv) { bv = v2; best = cb + 2; }
        float v3 = __fmul_rn(rq.w, obj); if (v3 > bv) { bv = v3; best = cb + 3; }
    }
    g_cls[b * PRE + t] = (float)best;
}

// ---------------- kernel 5: IoU bitmask (skewed SoA smem, gated div) ----------
__global__ void __launch_bounds__(256) iou_kernel() {
    int b = blockIdx.y;
    int warp = threadIdx.x >> 5, lane = threadIdx.x & 31;
    int r = blockIdx.x * 8 + warp;
    __shared__ float sx1[1056], sy1[1056], sx2[1056], sy2[1056], sar[1056];
    for (int j = threadIdx.x; j < PRE; j += 256) {
        float4 v = ((const float4*)g_boxes)[b * PRE + j];
        int jj = j + (j >> 5);                 // skew: lane-stride-32 -> conflict-free
        sx1[jj] = v.x; sy1[jj] = v.y; sx2[jj] = v.z; sy2[jj] = v.w;
        float w0 = fmaxf(__fsub_rn(v.z, v.x), 0.0f);
        float h0 = fmaxf(__fsub_rn(v.w, v.y), 0.0f);
        sar[jj] = __fmul_rn(w0, h0);
    }
    __syncthreads();
    int rr = r + (r >> 5);
    float bx1 = sx1[rr], by1 = sy1[rr], bx2 = sx2[rr], by2 = sy2[rr], ar = sar[rr];
    unsigned word = 0u;
    int jbase = lane * 32;
    if (jbase + 31 > r) {
        int jjb = lane * 33;
#pragma unroll
        for (int k = 0; k < 32; k++) {
            int j = jbase + k;
            if (j > r) {
                float lx = fmaxf(bx1, sx1[jjb + k]), ly = fmaxf(by1, sy1[jjb + k]);
                float rx = fminf(bx2, sx2[jjb + k]), ry = fminf(by2, sy2[jjb + k]);
                float iw = fmaxf(__fsub_rn(rx, lx), 0.0f);
                float ih = fmaxf(__fsub_rn(ry, ly), 0.0f);
                float inter = __fmul_rn(iw, ih);
                if (inter > 0.0f) {            // iou==0 can't exceed 0.45
                    float aj = sar[jjb + k];
                    float denom = __fadd_rn(__fsub_rn(__fadd_rn(ar, aj), inter), 1e-7f);
                    if ((inter / denom) > IOU_T) word |= (1u << k);
                }
            }
        }
    }
    g_mask[((size_t)b * PRE + r) * 32 + lane] = word;
}

// ---------------- kernel 6: NMS scan over smem-staged masks + top-300 out -------
__global__ void __launch_bounds__(256) nms_kernel(float* __restrict__ out) {
    extern __shared__ unsigned sh[];
    unsigned* smask  = sh;                          // PRE*32 words (128 KB)
    float*    sscore = (float*)(sh + PRE * 32);     // PRE floats
    __shared__ unsigned svalid[32];
    __shared__ unsigned skeep[32];
    __shared__ unsigned kpre[33];
    int b = blockIdx.x, t = threadIdx.x;

    // stage masks (coalesced uint4) + scores/validity
    const uint4* gm4 = (const uint4*)(g_mask + (size_t)b * PRE * 32);
    uint4* sm4 = (uint4*)smask;
    for (int j = t; j < PRE * 8; j += 256) sm4[j] = gm4[j];
    for (int it = 0; it < 4; it++) {
        int e = it * 256 + t;
        float sc = g_selscore[b * PRE + e];
        sscore[e] = sc;
        unsigned bl = __ballot_sync(0xffffffffu, sc > 0.0f);
        if ((t & 31) == 0) svalid[it * 8 + (t >> 5)] = bl;
    }
    __syncthreads();

    // warp 0: word-parallel scan (lane = distributed suppression word)
    if (t < 32) {
        unsigned sup = 0u, mykeep = 0u;
        for (int w = 0; w < 32; w++) {
            unsigned m[32];
#pragma unroll
            for (int k = 0; k < 32; k++) m[k] = smask[(w * 32 + k) * 32 + t];
            unsigned kw = 0u;
            if (t == w) {
                unsigned ss = sup, vw = svalid[w];
#pragma unroll
                for (int k = 0; k < 32; k++) {
                    unsigned bit = 1u << k;
                    if ((vw & bit) && !(ss & bit)) { kw |= bit; ss |= m[k]; }
                }
                sup = ss;
            }
            kw = __shfl_sync(0xffffffffu, kw, w);
            if (t == w) {
                mykeep = kw;
            } else {
#pragma unroll
                for (int k = 0; k < 32; k++)
                    if (kw & (1u << k)) sup |= m[k];
            }
        }
        skeep[t] = mykeep;
    }
    __syncthreads();

    if (t < 32) {
        unsigned acc = 0;
        for (int q = 0; q < 32; q++) {
            if (q == t) kpre[t] = acc;
            acc += __popc(skeep[q]);
        }
        if (t == 31) kpre[32] = acc;
    }
    __syncthreads();
    unsigned total = kpre[32];

    for (int e = t; e < PRE; e += 256) {
        int w = e >> 5, bit = e & 31;
        int rank = kpre[w] + __popc(skeep[w] & ((1u << bit) - 1u));
        bool kp = (skeep[w] >> bit) & 1u;
        int orow = -1; float osc = 0.0f;
        if (kp) {
            if (rank < MAXD) { orow = rank; osc = sscore[e]; }
        } else {
            int nr = e - rank;
            if ((int)total + nr < MAXD) orow = (int)total + nr;
        }
        if (orow >= 0) {
            float4 bx = ((const float4*)g_boxes)[b * PRE + e];
            float cc = g_cls[b * PRE + e];
            float* o = out + ((size_t)b * MAXD + orow) * 6;
            o[0] = bx.x; o[1] = bx.y; o[2] = bx.z; o[3] = bx.w;
            o[4] = osc;  o[5] = cc;
        }
    }
}

// ---------------- launch ----------------
extern "C" void kernel_launch(void* const* d_in, const int* in_sizes, int n_in,
                              void* d_out, int out_size) {
    const float* pred = (const float*)d_in[0];
    float* out = (float*)d_out;

    const int nms_smem = (PRE * 32 + PRE) * 4;      // 135168 bytes
    cudaFuncSetAttribute(nms_kernel, cudaFuncAttributeMaxDynamicSharedMemorySize, nms_smem);

    score_kernel<<<dim3((NANCH + 255) / 256, BATCH), 256>>>(pred);
    thresh_kernel<<<BATCH, 1024>>>();
    gatherk_kernel<<<dim3((NANCH / 4 + 255) / 256, BATCH), 256>>>();
    sortg_kernel<<<BATCH, 1024>>>(pred);
    iou_kernel<<<dim3(PRE / 8, BATCH), 256>>>();
    nms_kernel<<<BATCH, 256, nms_smem>>>(out);
}